// round 14
// baseline (speedup 1.0000x reference)
#include <cuda_runtime.h>
#include <cuda_bf16.h>

// Shapes (fixed): B=32, T=256, D=64, H=128, G=3H=384
#define B 32
#define T 256
#define D 64
#define H 128
#define G 384

// ---------------- scratch (device globals: allocation-free) ----------------
__device__ float g_w[B * D];
__device__ float g_vr[B * T * H];
__device__ float g_gi[B * T * G];

// ---------------- packed f32x2 helpers ----------------
__device__ __forceinline__ unsigned long long ffma2(unsigned long long a,
                                                    unsigned long long b,
                                                    unsigned long long c) {
    unsigned long long d;
    asm("fma.rn.f32x2 %0, %1, %2, %3;" : "=l"(d) : "l"(a), "l"(b), "l"(c));
    return d;
}
__device__ __forceinline__ float2 u2f(unsigned long long v) {
    float2 r;
    asm("mov.b64 {%0, %1}, %2;" : "=f"(r.x), "=f"(r.y) : "l"(v));
    return r;
}
__device__ __forceinline__ float sigf(float x) {
    return __fdividef(1.0f, 1.0f + __expf(-x));
}

// single dynamic-smem symbol (gi_kernel)
extern __shared__ float smdyn[];

// ---------------- kernel 0: prep = sim rows + per-batch w ------------------
__global__ __launch_bounds__(256) void prep_kernel(
    const float* __restrict__ E, const float* __restrict__ mm) {
    __shared__ float Es[D][H + 1];
    __shared__ float simS[D][D + 1];
    __shared__ float part[4][D];
    __shared__ float p[D], rs[D];
    int b = blockIdx.x, tid = threadIdx.x;
    int j = tid & (D - 1), grp = tid >> 6;

    for (int idx = tid; idx < D * H; idx += 256)
        Es[idx >> 7][idx & 127] = E[idx];
    __syncthreads();

    {
        float acc[16] = {};
#pragma unroll 4
        for (int k = 0; k < H; k++) {
            float ej = Es[j][k];
#pragma unroll
            for (int ii = 0; ii < 16; ii++)
                acc[ii] += ej * Es[grp * 16 + ii][k];
        }
#pragma unroll
        for (int ii = 0; ii < 16; ii++)
            simS[j][grp * 16 + ii] = fmaxf(acc[ii], 0.f);
    }

    const float* mb = mm + b * T * D;
    float s = 0.f;
#pragma unroll 8
    for (int t = grp * 64; t < (grp + 1) * 64; t++) s += mb[t * D + j];
    part[grp][j] = s;
    __syncthreads();
    if (tid < D) {
        float tot = part[0][j] + part[1][j] + part[2][j] + part[3][j];
        p[j] = 1.f - tot * (1.f / (float)T);
    }
    __syncthreads();
    if (tid < D) {
        float q = 0.f;
#pragma unroll 8
        for (int jj = 0; jj < D; jj++) q += p[jj] * simS[j][jj];
        rs[j] = fmaxf(p[j] * q + 1.f, 1e-6f);
    }
    __syncthreads();
    if (tid < D) {
        float acc = 0.f;
#pragma unroll 8
        for (int i = 0; i < D; i++) acc += p[i] * simS[j][i] / rs[i];
        g_w[b * D + j] = (p[j] * acc + 1.f / rs[j]) * (1.f / (float)D);
    }
}

// ---------------- kernel 1: visit_repr = c @ E + time_enc ------------------
__global__ __launch_bounds__(256) void vr_kernel(
    const float* __restrict__ x, const float* __restrict__ mm,
    const float* __restrict__ vt, const float* __restrict__ E) {
    __shared__ float Es[D * H];
    __shared__ float cs[32 * D];
    __shared__ float tv[32];
    __shared__ float freqs[64];
    int b = blockIdx.y, t0 = blockIdx.x * 32, tid = threadIdx.x;

    const float NEGC = -0.14391156831212787f;  // -ln(10000)/64
    if (tid < 64) freqs[tid] = __expf(NEGC * (float)tid);
    for (int idx = tid; idx < D * H; idx += 256) Es[idx] = E[idx];
    int base = b * T * D + t0 * D;
    for (int idx = tid; idx < 32 * D; idx += 256) {
        int j = idx & (D - 1);
        cs[idx] = x[base + idx] * (1.f - mm[base + idx]) * g_w[b * D + j];
    }
    if (tid < 32) tv[tid] = vt[b * T + t0 + tid];
    __syncthreads();

    int warp = tid >> 5, lane = tid & 31;
    float acc[4][4] = {};
#pragma unroll 4
    for (int j = 0; j < D; j++) {
        float e0 = Es[j * H + lane];
        float e1 = Es[j * H + lane + 32];
        float e2 = Es[j * H + lane + 64];
        float e3 = Es[j * H + lane + 96];
#pragma unroll
        for (int q = 0; q < 4; q++) {
            float c = cs[(warp * 4 + q) * D + j];
            acc[q][0] += c * e0; acc[q][1] += c * e1;
            acc[q][2] += c * e2; acc[q][3] += c * e3;
        }
    }
#pragma unroll
    for (int q = 0; q < 4; q++) {
        int tt = warp * 4 + q;
        float t = tv[tt];
        float* o = g_vr + (b * T + t0 + tt) * H;
#pragma unroll
        for (int m = 0; m < 4; m++) {
            int h = lane + 32 * m;
            int hm = (h < 64) ? h : h - 64;
            float ang = t * freqs[hm];
            float te = (h < 64) ? sinf(ang) : cosf(ang);
            o[h] = acc[q][m] + te;
        }
    }
}

// ---------------- kernel 2: gi = vr @ W_ih^T + biases ----------------------
#define W2S 66   // float2 stride
__global__ __launch_bounds__(256) void gi_kernel(
    const float* __restrict__ wih, const float* __restrict__ bih,
    const float* __restrict__ bhh) {
    float* vrs = smdyn;                                      // 64 x 128 floats
    float2* W2 = reinterpret_cast<float2*>(smdyn + 64 * H);  // [kp][g], str 66
    int bt0 = blockIdx.x * 64, g0 = blockIdx.y * 64, tid = threadIdx.x;

    for (int idx = tid; idx < 64 * H; idx += 256) vrs[idx] = g_vr[bt0 * H + idx];
    const float2* wih2 = reinterpret_cast<const float2*>(wih + g0 * H);
    for (int idx = tid; idx < 64 * 64; idx += 256) {
        int g = idx >> 6, kp = idx & 63;
        W2[kp * W2S + g] = wih2[g * 64 + kp];
    }
    __syncthreads();

    int warp = tid >> 5, lane = tid & 31;
    const float* vrow = vrs + warp * 8 * H;
    unsigned long long acc[8][2] = {};
#pragma unroll 4
    for (int kp = 0; kp < 64; kp++) {
        const unsigned long long* wrow =
            reinterpret_cast<const unsigned long long*>(W2 + kp * W2S);
        unsigned long long w0 = wrow[lane];
        unsigned long long w1 = wrow[lane + 32];
#pragma unroll
        for (int q = 0; q < 8; q++) {
            unsigned long long v =
                *reinterpret_cast<const unsigned long long*>(vrow + q * H + 2 * kp);
            acc[q][0] = ffma2(w0, v, acc[q][0]);
            acc[q][1] = ffma2(w1, v, acc[q][1]);
        }
    }
    bool rz = (g0 < 2 * H);
#pragma unroll
    for (int q = 0; q < 8; q++) {
        float* o = g_gi + (bt0 + warp * 8 + q) * G + g0;
#pragma unroll
        for (int m = 0; m < 2; m++) {
            float2 f = u2f(acc[q][m]);
            int g = lane + 32 * m;
            float bias = bih[g0 + g] + (rz ? bhh[g0 + g] : 0.f);
            o[g] = f.x + f.y + bias;
        }
    }
}

// ---------------- kernel 3: GRU — one gate per warp-group ------------------
// 32 blocks x 384 threads. Thread (gate = tid>>7, u = tid&127) holds ONE gate
// row of W_hh for unit u over FULL k in registers (64 ull = 128 regs; cap
// 170 @384thr -> ~35 regs slack). 3 warps/SMSP interleave the same FFMA2
// pipe floor, hiding LDS/MUFU latency; NO shuffles (complete dot product per
// thread). Cross-gate combine: sums[gate][u] in smem + barrier; gate-0 warps
// compute the gates once. gi for r/z (biases pre-folded by gi_kernel) is
// added into the stored sum; the n row stores sn + b_hh_n; gate-0 threads
// fetch gi_n themselves. h double-buffered; two barriers per step.
__global__ __launch_bounds__(384, 1) void gru_kernel(
    const float* __restrict__ whh, const float* __restrict__ bhh,
    const int* __restrict__ lengths, float* __restrict__ out) {
    __shared__ __align__(16) float hs[2][132];
    __shared__ float sums[3][132];
    int b = blockIdx.x, tid = threadIdx.x;
    int gate = tid >> 7, u = tid & 127;

    unsigned long long w[64];
    {
        const unsigned long long* pw =
            reinterpret_cast<const unsigned long long*>(whh + (gate * H + u) * H);
#pragma unroll
        for (int i = 0; i < 64; i++) w[i] = pw[i];
    }
    // n-gate threads add b_hh_n to their sum (kept outside r*(.) by algebra)
    float addc = (gate == 2) ? bhh[2 * H + u] : 0.f;
    int len = lengths[b];
    if (tid < 132) { hs[0][tid] = 0.f; hs[1][tid] = 0.f; }

    const float* gib = g_gi + b * T * G;
    float* ob = out + b * T * H;

    float hreg = 0.f;
    __syncthreads();

    for (int t = 0; t < T; t++) {
        const float* qq = gib + t * G;
        // r/z threads add their (pre-biased) gi; n threads add b_hh_n
        float giv = (gate == 2) ? addc : qq[gate * H + u];
        float ginv = (gate == 0) ? qq[2 * H + u] : 0.f;  // gi_n for gate calc

        const ulonglong2* h2 =
            reinterpret_cast<const ulonglong2*>(hs[t & 1]);
        unsigned long long a0 = 0ull, a1 = 0ull;
#pragma unroll
        for (int i = 0; i < 32; i++) {
            ulonglong2 hv = h2[i];                    // broadcast LDS.128
            a0 = ffma2(w[2 * i], hv.x, a0);
            a1 = ffma2(w[2 * i + 1], hv.y, a1);
        }
        float2 f0 = u2f(a0), f1 = u2f(a1);
        sums[gate][u] = (f0.x + f1.x) + (f0.y + f1.y) + giv;
        __syncthreads();                              // sums ready

        if (tid < 128) {                              // gate-0 warps compute
            float xr = sums[0][u];                    // = W_r.h + gi_r (+biases)
            float xz = sums[1][u];
            float xn = sums[2][u];                    // = W_n.h + b_hh_n
            float r = sigf(xr);
            float z = sigf(xz);
            float a = ginv + r * xn;
            float n = 1.f - __fdividef(2.f, __expf(2.f * a) + 1.f);
            float hn = n + z * (hreg - n);
            hreg = hn;
            hs[(t + 1) & 1][u] = hn;                  // write OTHER buffer
            ob[t * H + u] = (t < len) ? hn : 0.f;
        }
        __syncthreads();                              // h ready for next step
    }
}

// ---------------- launcher -------------------------------------------------
extern "C" void kernel_launch(void* const* d_in, const int* in_sizes, int n_in,
                              void* d_out, int out_size) {
    const float* x   = (const float*)d_in[0];
    const float* mm  = (const float*)d_in[1];
    const float* vt  = (const float*)d_in[2];
    const int*   len = (const int*)d_in[4];
    const float* E   = (const float*)d_in[5];
    const float* wih = (const float*)d_in[6];
    const float* whh = (const float*)d_in[7];
    const float* bih = (const float*)d_in[8];
    const float* bhh = (const float*)d_in[9];
    float* out = (float*)d_out;

    size_t gi_smem = 64 * H * sizeof(float) + 64 * W2S * sizeof(float2);
    cudaFuncSetAttribute(gi_kernel, cudaFuncAttributeMaxDynamicSharedMemorySize,
                         (int)gi_smem);

    prep_kernel<<<B, 256>>>(E, mm);
    vr_kernel<<<dim3(T / 32, B), 256>>>(x, mm, vt, E);
    gi_kernel<<<dim3(B * T / 64, 6), 256, gi_smem>>>(wih, bih, bhh);
    gru_kernel<<<B, 384>>>(whh, bhh, len, out);
}

// round 15
// speedup vs baseline: 1.3047x; 1.3047x over previous
#include <cuda_runtime.h>
#include <cuda_bf16.h>

// Shapes (fixed): B=32, T=256, D=64, H=128, G=3H=384
#define B 32
#define T 256
#define D 64
#define H 128
#define G 384

// ---------------- scratch (device globals: allocation-free) ----------------
__device__ float g_w[B * D];
__device__ float g_vr[B * T * H];
__device__ float g_gi[B * T * 4 * H];   // packed [bt][unit][r,z,n,pad]

// ---------------- packed f32x2 helpers ----------------
__device__ __forceinline__ unsigned long long ffma2(unsigned long long a,
                                                    unsigned long long b,
                                                    unsigned long long c) {
    unsigned long long d;
    asm("fma.rn.f32x2 %0, %1, %2, %3;" : "=l"(d) : "l"(a), "l"(b), "l"(c));
    return d;
}
__device__ __forceinline__ float2 u2f(unsigned long long v) {
    float2 r;
    asm("mov.b64 {%0, %1}, %2;" : "=f"(r.x), "=f"(r.y) : "l"(v));
    return r;
}
__device__ __forceinline__ float sigf(float x) {
    return __fdividef(1.0f, 1.0f + __expf(-x));
}
__device__ __forceinline__ float tanh_fast(float x) {
    float y;
    asm("tanh.approx.f32 %0, %1;" : "=f"(y) : "f"(x));
    return y;
}

// single dynamic-smem symbol (gi_kernel)
extern __shared__ float smdyn[];

// ---------------- kernel 0: prep = sim rows + per-batch w ------------------
__global__ __launch_bounds__(256) void prep_kernel(
    const float* __restrict__ E, const float* __restrict__ mm) {
    __shared__ float Es[D][H + 1];
    __shared__ float simS[D][D + 1];
    __shared__ float part[4][D];
    __shared__ float p[D], rs[D];
    int b = blockIdx.x, tid = threadIdx.x;
    int j = tid & (D - 1), grp = tid >> 6;

    for (int idx = tid; idx < D * H; idx += 256)
        Es[idx >> 7][idx & 127] = E[idx];
    __syncthreads();

    {
        float acc[16] = {};
#pragma unroll 4
        for (int k = 0; k < H; k++) {
            float ej = Es[j][k];
#pragma unroll
            for (int ii = 0; ii < 16; ii++)
                acc[ii] += ej * Es[grp * 16 + ii][k];
        }
#pragma unroll
        for (int ii = 0; ii < 16; ii++)
            simS[j][grp * 16 + ii] = fmaxf(acc[ii], 0.f);
    }

    const float* mb = mm + b * T * D;
    float s = 0.f;
#pragma unroll 8
    for (int t = grp * 64; t < (grp + 1) * 64; t++) s += mb[t * D + j];
    part[grp][j] = s;
    __syncthreads();
    if (tid < D) {
        float tot = part[0][j] + part[1][j] + part[2][j] + part[3][j];
        p[j] = 1.f - tot * (1.f / (float)T);
    }
    __syncthreads();
    if (tid < D) {
        float q = 0.f;
#pragma unroll 8
        for (int jj = 0; jj < D; jj++) q += p[jj] * simS[j][jj];
        rs[j] = fmaxf(p[j] * q + 1.f, 1e-6f);
    }
    __syncthreads();
    if (tid < D) {
        float acc = 0.f;
#pragma unroll 8
        for (int i = 0; i < D; i++) acc += p[i] * simS[j][i] / rs[i];
        g_w[b * D + j] = (p[j] * acc + 1.f / rs[j]) * (1.f / (float)D);
    }
}

// ---------------- kernel 1: visit_repr = c @ E + time_enc ------------------
__global__ __launch_bounds__(256) void vr_kernel(
    const float* __restrict__ x, const float* __restrict__ mm,
    const float* __restrict__ vt, const float* __restrict__ E) {
    __shared__ float Es[D * H];
    __shared__ float cs[32 * D];
    __shared__ float tv[32];
    __shared__ float freqs[64];
    int b = blockIdx.y, t0 = blockIdx.x * 32, tid = threadIdx.x;

    const float NEGC = -0.14391156831212787f;  // -ln(10000)/64
    if (tid < 64) freqs[tid] = __expf(NEGC * (float)tid);
    for (int idx = tid; idx < D * H; idx += 256) Es[idx] = E[idx];
    int base = b * T * D + t0 * D;
    for (int idx = tid; idx < 32 * D; idx += 256) {
        int j = idx & (D - 1);
        cs[idx] = x[base + idx] * (1.f - mm[base + idx]) * g_w[b * D + j];
    }
    if (tid < 32) tv[tid] = vt[b * T + t0 + tid];
    __syncthreads();

    int warp = tid >> 5, lane = tid & 31;
    float acc[4][4] = {};
#pragma unroll 4
    for (int j = 0; j < D; j++) {
        float e0 = Es[j * H + lane];
        float e1 = Es[j * H + lane + 32];
        float e2 = Es[j * H + lane + 64];
        float e3 = Es[j * H + lane + 96];
#pragma unroll
        for (int q = 0; q < 4; q++) {
            float c = cs[(warp * 4 + q) * D + j];
            acc[q][0] += c * e0; acc[q][1] += c * e1;
            acc[q][2] += c * e2; acc[q][3] += c * e3;
        }
    }
#pragma unroll
    for (int q = 0; q < 4; q++) {
        int tt = warp * 4 + q;
        float t = tv[tt];
        float* o = g_vr + (b * T + t0 + tt) * H;
#pragma unroll
        for (int m = 0; m < 4; m++) {
            int h = lane + 32 * m;
            int hm = (h < 64) ? h : h - 64;
            float ang = t * freqs[hm];
            float te = (h < 64) ? sinf(ang) : cosf(ang);
            o[h] = acc[q][m] + te;
        }
    }
}

// ---------------- kernel 2: gi = vr @ W_ih^T + biases, PACKED output -------
// Output layout: g_gi[bt*512 + u*4 + gate], gate: 0=r, 1=z, 2=n.
// r,z rows carry b_ih+b_hh; n rows carry b_ih only (b_hh_n applied in GRU).
#define W2S 66   // float2 stride
__global__ __launch_bounds__(256) void gi_kernel(
    const float* __restrict__ wih, const float* __restrict__ bih,
    const float* __restrict__ bhh) {
    float* vrs = smdyn;                                      // 64 x 128 floats
    float2* W2 = reinterpret_cast<float2*>(smdyn + 64 * H);  // [kp][g], str 66
    int bt0 = blockIdx.x * 64, g0 = blockIdx.y * 64, tid = threadIdx.x;

    for (int idx = tid; idx < 64 * H; idx += 256) vrs[idx] = g_vr[bt0 * H + idx];
    const float2* wih2 = reinterpret_cast<const float2*>(wih + g0 * H);
    for (int idx = tid; idx < 64 * 64; idx += 256) {
        int g = idx >> 6, kp = idx & 63;
        W2[kp * W2S + g] = wih2[g * 64 + kp];
    }
    __syncthreads();

    int warp = tid >> 5, lane = tid & 31;
    const float* vrow = vrs + warp * 8 * H;
    unsigned long long acc[8][2] = {};
#pragma unroll 4
    for (int kp = 0; kp < 64; kp++) {
        const unsigned long long* wrow =
            reinterpret_cast<const unsigned long long*>(W2 + kp * W2S);
        unsigned long long w0 = wrow[lane];
        unsigned long long w1 = wrow[lane + 32];
#pragma unroll
        for (int q = 0; q < 8; q++) {
            unsigned long long v =
                *reinterpret_cast<const unsigned long long*>(vrow + q * H + 2 * kp);
            acc[q][0] = ffma2(w0, v, acc[q][0]);
            acc[q][1] = ffma2(w1, v, acc[q][1]);
        }
    }
    bool rz = (g0 < 2 * H);
#pragma unroll
    for (int q = 0; q < 8; q++) {
        float* o = g_gi + (size_t)(bt0 + warp * 8 + q) * (4 * H);
#pragma unroll
        for (int m = 0; m < 2; m++) {
            float2 f = u2f(acc[q][m]);
            int g = g0 + lane + 32 * m;           // global gate-row index
            float bias = bih[g] + (rz ? bhh[g] : 0.f);
            o[(g & 127) * 4 + (g >> 7)] = f.x + f.y + bias;
        }
    }
}

// ---------------- kernel 3: GRU recurrence (champion + packed gi + HW tanh)
// 32 blocks x 256 threads, thread (g = tid>>1, half = tid&1) holds all 3 gate
// rows of W_hh over its k-half in registers. h double-buffered; ONE barrier
// per step; 3 SHFL.BFLY(1). Changes vs 186.7us champion: (a) gi is ONE
// LDG.128 (packed r,z,n) instead of 3 scattered LDG.32; (b) the n-gate tanh
// uses MUFU.TANH (longest serial chain -40 cyc); sigmoids unchanged.
__global__ __launch_bounds__(256, 1) void gru_kernel(
    const float* __restrict__ whh, const float* __restrict__ bhh,
    const int* __restrict__ lengths, float* __restrict__ out) {
    __shared__ __align__(16) float hs[2][136];
    int b = blockIdx.x, tid = threadIdx.x;
    int g = tid >> 1, half = tid & 1;

    unsigned long long wr[32], wz[32], wn[32];
    {
        const unsigned long long* pr =
            reinterpret_cast<const unsigned long long*>(whh + g * H + half * 64);
        const unsigned long long* pz =
            reinterpret_cast<const unsigned long long*>(whh + (H + g) * H + half * 64);
        const unsigned long long* pn =
            reinterpret_cast<const unsigned long long*>(whh + (2 * H + g) * H + half * 64);
#pragma unroll
        for (int i = 0; i < 32; i++) wr[i] = pr[i];
#pragma unroll
        for (int i = 0; i < 32; i++) wz[i] = pz[i];
#pragma unroll
        for (int i = 0; i < 32; i++) wn[i] = pn[i];
    }
    float bn = bhh[2 * H + g];          // r,z biases pre-folded into g_gi
    int len = lengths[b];
    if (tid < 136) { hs[0][tid] = 0.f; hs[1][tid] = 0.f; }

    const float4* gib4 =
        reinterpret_cast<const float4*>(g_gi + (size_t)b * T * 4 * H);
    float* ob = out + b * T * H;
    int hidx = (g < 64) ? g : g + 4;

    float hreg = 0.f;
    __syncthreads();

#pragma unroll 2
    for (int t = 0; t < T; t++) {
        // current-step gi: ONE LDG.128, consumed after the gemv (hidden)
        float4 gi = gib4[t * H + g];    // x=r, y=z, z=n

        const ulonglong2* h2 =
            reinterpret_cast<const ulonglong2*>(hs[t & 1] + half * 68);
        unsigned long long ar = 0ull, az = 0ull, an = 0ull;
#pragma unroll
        for (int i = 0; i < 16; i++) {
            ulonglong2 hv = h2[i];                    // broadcast LDS.128
            ar = ffma2(wr[2 * i], hv.x, ar);
            az = ffma2(wz[2 * i], hv.x, az);
            an = ffma2(wn[2 * i], hv.x, an);
            ar = ffma2(wr[2 * i + 1], hv.y, ar);
            az = ffma2(wz[2 * i + 1], hv.y, az);
            an = ffma2(wn[2 * i + 1], hv.y, an);
        }
        float2 fr = u2f(ar), fz = u2f(az), fn = u2f(an);
        float sr = fr.x + fr.y, sz = fz.x + fz.y, sn = fn.x + fn.y;
        sr += __shfl_xor_sync(0xffffffffu, sr, 1);
        sz += __shfl_xor_sync(0xffffffffu, sz, 1);
        sn += __shfl_xor_sync(0xffffffffu, sn, 1);

        float r = sigf(gi.x + sr);                    // biases pre-folded
        float z = sigf(gi.y + sz);
        float a = gi.z + r * (sn + bn);
        float n = tanh_fast(a);                       // MUFU.TANH
        float hn = n + z * (hreg - n);
        hreg = hn;
        if (!half) {
            hs[(t + 1) & 1][hidx] = hn;               // write OTHER buffer
            ob[t * H + g] = (t < len) ? hn : 0.f;
        }
        __syncthreads();                              // write -> next read
    }
}

// ---------------- launcher -------------------------------------------------
extern "C" void kernel_launch(void* const* d_in, const int* in_sizes, int n_in,
                              void* d_out, int out_size) {
    const float* x   = (const float*)d_in[0];
    const float* mm  = (const float*)d_in[1];
    const float* vt  = (const float*)d_in[2];
    const int*   len = (const int*)d_in[4];
    const float* E   = (const float*)d_in[5];
    const float* wih = (const float*)d_in[6];
    const float* whh = (const float*)d_in[7];
    const float* bih = (const float*)d_in[8];
    const float* bhh = (const float*)d_in[9];
    float* out = (float*)d_out;

    size_t gi_smem = 64 * H * sizeof(float) + 64 * W2S * sizeof(float2);
    cudaFuncSetAttribute(gi_kernel, cudaFuncAttributeMaxDynamicSharedMemorySize,
                         (int)gi_smem);

    prep_kernel<<<B, 256>>>(E, mm);
    vr_kernel<<<dim3(T / 32, B), 256>>>(x, mm, vt, E);
    gi_kernel<<<dim3(B * T / 64, 6), 256, gi_smem>>>(wih, bih, bhh);
    gru_kernel<<<B, 256>>>(whh, bhh, len, out);
}

// round 16
// speedup vs baseline: 1.3211x; 1.0126x over previous
#include <cuda_runtime.h>
#include <cuda_bf16.h>

// Shapes (fixed): B=32, T=256, D=64, H=128, G=3H=384
#define B 32
#define T 256
#define D 64
#define H 128
#define G 384

// ---------------- scratch (device globals: allocation-free) ----------------
__device__ float g_w[B * D];
__device__ float g_vr[B * T * H];
__device__ float g_gi[B * T * 4 * H];   // packed [bt][unit][r,z,n,pad]

// ---------------- packed f32x2 helpers ----------------
__device__ __forceinline__ unsigned long long ffma2(unsigned long long a,
                                                    unsigned long long b,
                                                    unsigned long long c) {
    unsigned long long d;
    asm("fma.rn.f32x2 %0, %1, %2, %3;" : "=l"(d) : "l"(a), "l"(b), "l"(c));
    return d;
}
__device__ __forceinline__ float2 u2f(unsigned long long v) {
    float2 r;
    asm("mov.b64 {%0, %1}, %2;" : "=f"(r.x), "=f"(r.y) : "l"(v));
    return r;
}
__device__ __forceinline__ float tanh_fast(float x) {
    float y;
    asm("tanh.approx.f32 %0, %1;" : "=f"(y) : "f"(x));
    return y;
}
// sigmoid via MUFU.TANH: 3 ops, 1 MUFU (vs 5 ops, 2 MUFU)
__device__ __forceinline__ float sigf(float x) {
    return fmaf(0.5f, tanh_fast(0.5f * x), 0.5f);
}

// single dynamic-smem symbol (gi_kernel)
extern __shared__ float smdyn[];

// ---------------- kernel 0: prep = sim rows + per-batch w ------------------
__global__ __launch_bounds__(256) void prep_kernel(
    const float* __restrict__ E, const float* __restrict__ mm) {
    __shared__ float Es[D][H + 1];
    __shared__ float simS[D][D + 1];
    __shared__ float part[4][D];
    __shared__ float p[D], rs[D];
    int b = blockIdx.x, tid = threadIdx.x;
    int j = tid & (D - 1), grp = tid >> 6;

    for (int idx = tid; idx < D * H; idx += 256)
        Es[idx >> 7][idx & 127] = E[idx];
    __syncthreads();

    {
        float acc[16] = {};
#pragma unroll 4
        for (int k = 0; k < H; k++) {
            float ej = Es[j][k];
#pragma unroll
            for (int ii = 0; ii < 16; ii++)
                acc[ii] += ej * Es[grp * 16 + ii][k];
        }
#pragma unroll
        for (int ii = 0; ii < 16; ii++)
            simS[j][grp * 16 + ii] = fmaxf(acc[ii], 0.f);
    }

    const float* mb = mm + b * T * D;
    float s = 0.f;
#pragma unroll 8
    for (int t = grp * 64; t < (grp + 1) * 64; t++) s += mb[t * D + j];
    part[grp][j] = s;
    __syncthreads();
    if (tid < D) {
        float tot = part[0][j] + part[1][j] + part[2][j] + part[3][j];
        p[j] = 1.f - tot * (1.f / (float)T);
    }
    __syncthreads();
    if (tid < D) {
        float q = 0.f;
#pragma unroll 8
        for (int jj = 0; jj < D; jj++) q += p[jj] * simS[j][jj];
        rs[j] = fmaxf(p[j] * q + 1.f, 1e-6f);
    }
    __syncthreads();
    if (tid < D) {
        float acc = 0.f;
#pragma unroll 8
        for (int i = 0; i < D; i++) acc += p[i] * simS[j][i] / rs[i];
        g_w[b * D + j] = (p[j] * acc + 1.f / rs[j]) * (1.f / (float)D);
    }
}

// ---------------- kernel 1: visit_repr = c @ E + time_enc ------------------
__global__ __launch_bounds__(256) void vr_kernel(
    const float* __restrict__ x, const float* __restrict__ mm,
    const float* __restrict__ vt, const float* __restrict__ E) {
    __shared__ float Es[D * H];
    __shared__ float cs[32 * D];
    __shared__ float tv[32];
    __shared__ float freqs[64];
    int b = blockIdx.y, t0 = blockIdx.x * 32, tid = threadIdx.x;

    const float NEGC = -0.14391156831212787f;  // -ln(10000)/64
    if (tid < 64) freqs[tid] = __expf(NEGC * (float)tid);
    for (int idx = tid; idx < D * H; idx += 256) Es[idx] = E[idx];
    int base = b * T * D + t0 * D;
    for (int idx = tid; idx < 32 * D; idx += 256) {
        int j = idx & (D - 1);
        cs[idx] = x[base + idx] * (1.f - mm[base + idx]) * g_w[b * D + j];
    }
    if (tid < 32) tv[tid] = vt[b * T + t0 + tid];
    __syncthreads();

    int warp = tid >> 5, lane = tid & 31;
    float acc[4][4] = {};
#pragma unroll 4
    for (int j = 0; j < D; j++) {
        float e0 = Es[j * H + lane];
        float e1 = Es[j * H + lane + 32];
        float e2 = Es[j * H + lane + 64];
        float e3 = Es[j * H + lane + 96];
#pragma unroll
        for (int q = 0; q < 4; q++) {
            float c = cs[(warp * 4 + q) * D + j];
            acc[q][0] += c * e0; acc[q][1] += c * e1;
            acc[q][2] += c * e2; acc[q][3] += c * e3;
        }
    }
#pragma unroll
    for (int q = 0; q < 4; q++) {
        int tt = warp * 4 + q;
        float t = tv[tt];
        float* o = g_vr + (b * T + t0 + tt) * H;
#pragma unroll
        for (int m = 0; m < 4; m++) {
            int h = lane + 32 * m;
            int hm = (h < 64) ? h : h - 64;
            float ang = t * freqs[hm];
            float te = (h < 64) ? sinf(ang) : cosf(ang);
            o[h] = acc[q][m] + te;
        }
    }
}

// ---------------- kernel 2: gi = vr @ W_ih^T + biases, PACKED output -------
// Output layout: g_gi[bt*512 + u*4 + gate], gate: 0=r, 1=z, 2=n.
// r,z rows carry b_ih+b_hh; n rows carry b_ih only (b_hh_n applied in GRU).
#define W2S 66   // float2 stride
__global__ __launch_bounds__(256) void gi_kernel(
    const float* __restrict__ wih, const float* __restrict__ bih,
    const float* __restrict__ bhh) {
    float* vrs = smdyn;                                      // 64 x 128 floats
    float2* W2 = reinterpret_cast<float2*>(smdyn + 64 * H);  // [kp][g], str 66
    int bt0 = blockIdx.x * 64, g0 = blockIdx.y * 64, tid = threadIdx.x;

    for (int idx = tid; idx < 64 * H; idx += 256) vrs[idx] = g_vr[bt0 * H + idx];
    const float2* wih2 = reinterpret_cast<const float2*>(wih + g0 * H);
    for (int idx = tid; idx < 64 * 64; idx += 256) {
        int g = idx >> 6, kp = idx & 63;
        W2[kp * W2S + g] = wih2[g * 64 + kp];
    }
    __syncthreads();

    int warp = tid >> 5, lane = tid & 31;
    const float* vrow = vrs + warp * 8 * H;
    unsigned long long acc[8][2] = {};
#pragma unroll 4
    for (int kp = 0; kp < 64; kp++) {
        const unsigned long long* wrow =
            reinterpret_cast<const unsigned long long*>(W2 + kp * W2S);
        unsigned long long w0 = wrow[lane];
        unsigned long long w1 = wrow[lane + 32];
#pragma unroll
        for (int q = 0; q < 8; q++) {
            unsigned long long v =
                *reinterpret_cast<const unsigned long long*>(vrow + q * H + 2 * kp);
            acc[q][0] = ffma2(w0, v, acc[q][0]);
            acc[q][1] = ffma2(w1, v, acc[q][1]);
        }
    }
    bool rz = (g0 < 2 * H);
#pragma unroll
    for (int q = 0; q < 8; q++) {
        float* o = g_gi + (size_t)(bt0 + warp * 8 + q) * (4 * H);
#pragma unroll
        for (int m = 0; m < 2; m++) {
            float2 f = u2f(acc[q][m]);
            int g = g0 + lane + 32 * m;           // global gate-row index
            float bias = bih[g] + (rz ? bhh[g] : 0.f);
            o[(g & 127) * 4 + (g >> 7)] = f.x + f.y + bias;
        }
    }
}

// ---------------- kernel 3: GRU recurrence (R15 champion + TANH sigmoids) --
// 32 blocks x 256 threads, thread (g = tid>>1, half = tid&1) holds all 3 gate
// rows of W_hh over its k-half in registers. h double-buffered; ONE barrier
// per step; 3 SHFL.BFLY(1); packed gi via ONE LDG.128. Change vs 180.3us
// champion: both sigmoids use the MUFU.TANH form (3 ops/1 MUFU each vs
// 5 ops/2 MUFU), shortening the serial r->a->n->hn tail by ~13 cyc and
// freeing 4 MUFU issue slots per thread-step.
__global__ __launch_bounds__(256, 1) void gru_kernel(
    const float* __restrict__ whh, const float* __restrict__ bhh,
    const int* __restrict__ lengths, float* __restrict__ out) {
    __shared__ __align__(16) float hs[2][136];
    int b = blockIdx.x, tid = threadIdx.x;
    int g = tid >> 1, half = tid & 1;

    unsigned long long wr[32], wz[32], wn[32];
    {
        const unsigned long long* pr =
            reinterpret_cast<const unsigned long long*>(whh + g * H + half * 64);
        const unsigned long long* pz =
            reinterpret_cast<const unsigned long long*>(whh + (H + g) * H + half * 64);
        const unsigned long long* pn =
            reinterpret_cast<const unsigned long long*>(whh + (2 * H + g) * H + half * 64);
#pragma unroll
        for (int i = 0; i < 32; i++) wr[i] = pr[i];
#pragma unroll
        for (int i = 0; i < 32; i++) wz[i] = pz[i];
#pragma unroll
        for (int i = 0; i < 32; i++) wn[i] = pn[i];
    }
    float bn = bhh[2 * H + g];          // r,z biases pre-folded into g_gi
    int len = lengths[b];
    if (tid < 136) { hs[0][tid] = 0.f; hs[1][tid] = 0.f; }

    const float4* gib4 =
        reinterpret_cast<const float4*>(g_gi + (size_t)b * T * 4 * H);
    float* ob = out + b * T * H;
    int hidx = (g < 64) ? g : g + 4;

    float hreg = 0.f;
    __syncthreads();

#pragma unroll 2
    for (int t = 0; t < T; t++) {
        // current-step gi: ONE LDG.128, consumed after the gemv (hidden)
        float4 gi = gib4[t * H + g];    // x=r, y=z, z=n

        const ulonglong2* h2 =
            reinterpret_cast<const ulonglong2*>(hs[t & 1] + half * 68);
        unsigned long long ar = 0ull, az = 0ull, an = 0ull;
#pragma unroll
        for (int i = 0; i < 16; i++) {
            ulonglong2 hv = h2[i];                    // broadcast LDS.128
            ar = ffma2(wr[2 * i], hv.x, ar);
            az = ffma2(wz[2 * i], hv.x, az);
            an = ffma2(wn[2 * i], hv.x, an);
            ar = ffma2(wr[2 * i + 1], hv.y, ar);
            az = ffma2(wz[2 * i + 1], hv.y, az);
            an = ffma2(wn[2 * i + 1], hv.y, an);
        }
        float2 fr = u2f(ar), fz = u2f(az), fn = u2f(an);
        float sr = fr.x + fr.y, sz = fz.x + fz.y, sn = fn.x + fn.y;
        sr += __shfl_xor_sync(0xffffffffu, sr, 1);
        sz += __shfl_xor_sync(0xffffffffu, sz, 1);
        sn += __shfl_xor_sync(0xffffffffu, sn, 1);

        float r = sigf(gi.x + sr);                    // MUFU.TANH sigmoid
        float z = sigf(gi.y + sz);
        float a = gi.z + r * (sn + bn);
        float n = tanh_fast(a);                       // MUFU.TANH
        float hn = n + z * (hreg - n);
        hreg = hn;
        if (!half) {
            hs[(t + 1) & 1][hidx] = hn;               // write OTHER buffer
            ob[t * H + g] = (t < len) ? hn : 0.f;
        }
        __syncthreads();                              // write -> next read
    }
}

// ---------------- launcher -------------------------------------------------
extern "C" void kernel_launch(void* const* d_in, const int* in_sizes, int n_in,
                              void* d_out, int out_size) {
    const float* x   = (const float*)d_in[0];
    const float* mm  = (const float*)d_in[1];
    const float* vt  = (const float*)d_in[2];
    const int*   len = (const int*)d_in[4];
    const float* E   = (const float*)d_in[5];
    const float* wih = (const float*)d_in[6];
    const float* whh = (const float*)d_in[7];
    const float* bih = (const float*)d_in[8];
    const float* bhh = (const float*)d_in[9];
    float* out = (float*)d_out;

    size_t gi_smem = 64 * H * sizeof(float) + 64 * W2S * sizeof(float2);
    cudaFuncSetAttribute(gi_kernel, cudaFuncAttributeMaxDynamicSharedMemorySize,
                         (int)gi_smem);

    prep_kernel<<<B, 256>>>(E, mm);
    vr_kernel<<<dim3(T / 32, B), 256>>>(x, mm, vt, E);
    gi_kernel<<<dim3(B * T / 64, 6), 256, gi_smem>>>(wih, bih, bhh);
    gru_kernel<<<B, 256>>>(whh, bhh, len, out);
}